// round 15
// baseline (speedup 1.0000x reference)
#include <cuda_runtime.h>
#include <cuda_fp16.h>
#include <cstdint>

#define SS   2048
#define DQ   4096
#define DKV  1024
#define SCL  (0.08838834764831845f * 1.4426950408889634f)

// smem: 3 K/V stages, 32KB each (K@+0, V@+16K). Q staged over stages 0-1.
#define SMEM_BYTES 98304

// fp16 K/V scratch: 4096 tokens x 1024 dims x 2B = 8MB each
__device__ uint4 g_kh[524288];
__device__ uint4 g_vh[524288];

__device__ __forceinline__ uint32_t smem_u32(const void* p) {
    uint32_t a;
    asm("{ .reg .u64 t; cvta.to.shared.u64 t, %1; cvt.u32.u64 %0, t; }" : "=r"(a) : "l"(p));
    return a;
}
__device__ __forceinline__ float fast_ex2(float x) {
    float y; asm("ex2.approx.ftz.f32 %0, %1;" : "=f"(y) : "f"(x)); return y;
}
__device__ __forceinline__ void ldsm_x4(uint32_t* r, uint32_t addr) {
    asm volatile("ldmatrix.sync.aligned.m8n8.x4.shared.b16 {%0,%1,%2,%3}, [%4];"
        : "=r"(r[0]), "=r"(r[1]), "=r"(r[2]), "=r"(r[3]) : "r"(addr));
}
__device__ __forceinline__ void ldsm_x4_t(uint32_t* r, uint32_t addr) {
    asm volatile("ldmatrix.sync.aligned.m8n8.x4.trans.shared.b16 {%0,%1,%2,%3}, [%4];"
        : "=r"(r[0]), "=r"(r[1]), "=r"(r[2]), "=r"(r[3]) : "r"(addr));
}
__device__ __forceinline__ void mma16816(float* d, const uint32_t* a, const uint32_t* b) {
    asm volatile("mma.sync.aligned.m16n8k16.row.col.f32.f16.f16.f32 "
        "{%0,%1,%2,%3},{%4,%5,%6,%7},{%8,%9},{%0,%1,%2,%3};"
        : "+f"(d[0]), "+f"(d[1]), "+f"(d[2]), "+f"(d[3])
        : "r"(a[0]), "r"(a[1]), "r"(a[2]), "r"(a[3]), "r"(b[0]), "r"(b[1]));
}
__device__ __forceinline__ uint32_t packh2(float a, float b) {
    __half2 h = __floats2half2_rn(a, b);
    return *(uint32_t*)&h;
}
__device__ __forceinline__ void cp16(uint32_t dst, const void* src) {
    asm volatile("cp.async.cg.shared.global [%0], [%1], 16;" :: "r"(dst), "l"(src));
}

// ---- K/V fp32 -> fp16 convert (one pass, 8 elems/thread/tensor) ----
__global__ void __launch_bounds__(256)
cvt_kv(const float* __restrict__ k, const float* __restrict__ v)
{
    size_t i = (size_t)blockIdx.x * 256 + threadIdx.x;   // 0..524287
    const float4* ks = (const float4*)k + 2 * i;
    float4 a = ks[0], c = ks[1];
    g_kh[i] = make_uint4(packh2(a.x, a.y), packh2(a.z, a.w),
                         packh2(c.x, c.y), packh2(c.z, c.w));
    const float4* vs = (const float4*)v + 2 * i;
    a = vs[0]; c = vs[1];
    g_vh[i] = make_uint4(packh2(a.x, a.y), packh2(a.z, a.w),
                         packh2(c.x, c.y), packh2(c.z, c.w));
}

// CTA: 4 heads x 32 tokens = 128 q-rows, 256 threads (8 warps), BN=64 keys/tile.
// Warp w: rows w*16..w*16+15 (head = w>>1, tokens q0 + (w&1)*16 ..).
// Each warp: S = Q(16xK) @ K^T(64 keys), exp in regs, O += P(reg) @ V (full hd).
// No P shared-memory roundtrip: QK C-fragments ARE the PV A-fragments.
// Diagonal tile: warp-uniform loop truncation skips fully-masked key chunks.
__global__ void __launch_bounds__(256, 1)
attn_hmma12(const float* __restrict__ q, float* __restrict__ out)
{
    extern __shared__ char sm[];
    const uint32_t sb = smem_u32(sm);

    const int tid  = threadIdx.x;
    const int warp = tid >> 5, lane = tid & 31;
    const int qb = 63 - (int)blockIdx.x;      // longest CTAs first
    const int kv = blockIdx.y, b = blockIdx.z;
    const int q0 = qb * 32;
    const int hbase = kv * 4;
    const int ntiles = (qb >> 1) + 1;
    const int m  = lane >> 3;

    // ---- stage Q fp16 (pre-scaled) into stage-0/1 region, 256B rows, swizzled ----
    #pragma unroll
    for (int it = 0; it < 8; ++it) {
        int id  = tid + 256 * it;
        int row = id >> 4, c16 = id & 15;
        int token = q0 + (row & 31);
        int head  = hbase + (row >> 5);
        const float4* gp = (const float4*)(q + (size_t)(b * SS + token) * DQ
                                             + head * 128 + c16 * 8);
        float4 f0 = gp[0], f1 = gp[1];
        uint32_t h0 = packh2(f0.x * SCL, f0.y * SCL);
        uint32_t h1 = packh2(f0.z * SCL, f0.w * SCL);
        uint32_t h2 = packh2(f1.x * SCL, f1.y * SCL);
        uint32_t h3 = packh2(f1.z * SCL, f1.w * SCL);
        uint32_t addr = sb + row * 256 + ((c16 ^ (row & 7)) << 4);
        asm volatile("st.shared.v4.b32 [%0],{%1,%2,%3,%4};"
            :: "r"(addr), "r"(h0), "r"(h1), "r"(h2), "r"(h3));
    }
    __syncthreads();

    // ---- persistent Q fragments, M=16: qf[kstep][4] (32 regs) ----
    uint32_t qf[8][4];
    {
        int row = warp * 16 + (lane & 7) + ((lane >> 3) & 1) * 8;
        #pragma unroll
        for (int ks = 0; ks < 8; ++ks) {
            int chunk = ks * 2 + (lane >> 4);
            ldsm_x4(qf[ks], sb + row * 256 + ((chunk ^ (row & 7)) << 4));
        }
    }
    __syncthreads();   // Q region free for cp.async stages

    // ---- cp.async one K/V tile into stage jt%3 (fp16 source, no regs held) ----
    auto issue = [&](int jt) {
        size_t base = ((size_t)(b * SS + jt * 64) * DKV + kv * 128) * 2;
        const char* gk = (const char*)g_kh + base;
        const char* gv = (const char*)g_vh + base;
        uint32_t st = sb + 32768u * (uint32_t)(jt % 3);
        #pragma unroll
        for (int i = 0; i < 4; ++i) {
            int idx = tid + 256 * i;
            int row = idx >> 4, c16 = idx & 15;
            uint32_t d = st + row * 256 + ((c16 ^ (row & 7)) << 4);
            size_t so = (size_t)row * (DKV * 2) + c16 * 16;
            cp16(d,         gk + so);
            cp16(d + 16384, gv + so);
        }
        asm volatile("cp.async.commit_group;" ::: "memory");
    };

    issue(0);
    if (1 < ntiles) issue(1);

    float o[16][4];                           // 64 regs
    #pragma unroll
    for (int i = 0; i < 16; ++i)
        #pragma unroll
        for (int j = 0; j < 4; ++j) o[i][j] = 0.0f;
    float lsum0 = 0.0f, lsum1 = 0.0f;

    const int tok0 = q0 + (warp & 1) * 16 + (lane >> 2);
    const int kgmax = q0 + (warp & 1) * 16 + 15;   // warp's max valid key

    for (int jt = 0; jt < ntiles; ++jt) {
        if (jt + 1 < ntiles) asm volatile("cp.async.wait_group 1;" ::: "memory");
        else                 asm volatile("cp.async.wait_group 0;" ::: "memory");
        __syncthreads();     // stage jt%3 visible CTA-wide (only barrier per tile)

        const uint32_t sK = sb + 32768u * (uint32_t)(jt % 3);
        const uint32_t sV = sK + 16384;

        float s[8][4];
        #pragma unroll
        for (int n2 = 0; n2 < 8; ++n2)
            #pragma unroll
            for (int j = 0; j < 4; ++j) s[n2][j] = 0.0f;

        uint32_t pa[4][4];

        if (jt + 1 < ntiles) {
            // ---- interior tile: branch-free (all keys valid for all rows) ----
            #pragma unroll
            for (int ks2 = 0; ks2 < 4; ++ks2) {
                #pragma unroll
                for (int n2 = 0; n2 < 8; ++n2) {
                    uint32_t kb[4];
                    int kr = n2 * 8 + (lane & 7);
                    int chunk = ks2 * 4 + m;
                    ldsm_x4(kb, sK + kr * 256 + ((chunk ^ (kr & 7)) << 4));
                    mma16816(s[n2], qf[2*ks2],   kb);
                    mma16816(s[n2], qf[2*ks2+1], kb + 2);
                }
            }
            #pragma unroll
            for (int n2 = 0; n2 < 8; ++n2) {
                float e0 = fast_ex2(s[n2][0]);
                float e1 = fast_ex2(s[n2][1]);
                float e2 = fast_ex2(s[n2][2]);
                float e3 = fast_ex2(s[n2][3]);
                lsum0 += e0 + e1;
                lsum1 += e2 + e3;
                pa[n2 >> 1][(n2 & 1) * 2]     = packh2(e0, e1);
                pa[n2 >> 1][(n2 & 1) * 2 + 1] = packh2(e2, e3);
            }

            if (jt + 2 < ntiles) issue(jt + 2);

            #pragma unroll
            for (int ks2 = 0; ks2 < 4; ++ks2) {
                int Vrow = ks2 * 16 + (m & 1) * 8 + (lane & 7);
                #pragma unroll
                for (int n2o = 0; n2o < 16; n2o += 2) {
                    uint32_t vb[4];
                    int chunk = n2o + (m >> 1);
                    ldsm_x4_t(vb, sV + Vrow * 256 + ((chunk ^ (Vrow & 7)) << 4));
                    mma16816(o[n2o],     pa[ks2], vb);
                    mma16816(o[n2o + 1], pa[ks2], vb + 2);
                }
            }
        } else {
            // ---- diagonal tile: truncate loops at warp's max valid key ----
            const int n2lim  = ((kgmax - jt * 64) >> 3) + 1;   // 2/4 (even qb), 6/8 (odd)
            const int ks2lim = ((kgmax - jt * 64) >> 4) + 1;   // 1/2 or 3/4

            for (int ks2 = 0; ks2 < 4; ++ks2) {
                for (int n2 = 0; n2 < n2lim; ++n2) {
                    uint32_t kb[4];
                    int kr = n2 * 8 + (lane & 7);
                    int chunk = ks2 * 4 + m;
                    ldsm_x4(kb, sK + kr * 256 + ((chunk ^ (kr & 7)) << 4));
                    mma16816(s[n2], qf[2*ks2],   kb);
                    mma16816(s[n2], qf[2*ks2+1], kb + 2);
                }
            }
            // full masked softmax: skipped groups (s=0) are masked to exact 0
            #pragma unroll
            for (int n2 = 0; n2 < 8; ++n2) {
                int kg = jt * 64 + n2 * 8 + (lane & 3) * 2;
                float e0 = (kg     <= tok0)     ? fast_ex2(s[n2][0]) : 0.0f;
                float e1 = (kg + 1 <= tok0)     ? fast_ex2(s[n2][1]) : 0.0f;
                float e2 = (kg     <= tok0 + 8) ? fast_ex2(s[n2][2]) : 0.0f;
                float e3 = (kg + 1 <= tok0 + 8) ? fast_ex2(s[n2][3]) : 0.0f;
                lsum0 += e0 + e1;
                lsum1 += e2 + e3;
                pa[n2 >> 1][(n2 & 1) * 2]     = packh2(e0, e1);
                pa[n2 >> 1][(n2 & 1) * 2 + 1] = packh2(e2, e3);
            }

            // PV: only key-chunks containing any valid key (pa beyond is all-zero)
            for (int ks2 = 0; ks2 < ks2lim; ++ks2) {
                int Vrow = ks2 * 16 + (m & 1) * 8 + (lane & 7);
                #pragma unroll
                for (int n2o = 0; n2o < 16; n2o += 2) {
                    uint32_t vb[4];
                    int chunk = n2o + (m >> 1);
                    ldsm_x4_t(vb, sV + Vrow * 256 + ((chunk ^ (Vrow & 7)) << 4));
                    mma16816(o[n2o],     pa[ks2], vb);
                    mma16816(o[n2o + 1], pa[ks2], vb + 2);
                }
            }
        }
    }

    // ---- epilogue: reduce l over the 4 lanes sharing a row, normalize, store ----
    lsum0 += __shfl_xor_sync(0xffffffffu, lsum0, 1);
    lsum0 += __shfl_xor_sync(0xffffffffu, lsum0, 2);
    lsum1 += __shfl_xor_sync(0xffffffffu, lsum1, 1);
    lsum1 += __shfl_xor_sync(0xffffffffu, lsum1, 2);
    float inv0 = 1.0f / lsum0, inv1 = 1.0f / lsum1;

    const int head = hbase + (warp >> 1);
    float* r0p = out + (size_t)(b * SS + tok0) * DQ + head * 128 + (lane & 3) * 2;
    float* r1p = r0p + (size_t)8 * DQ;
    #pragma unroll
    for (int n2o = 0; n2o < 16; ++n2o) {
        *(float2*)(r0p + n2o * 8) =
            make_float2(o[n2o][0] * inv0, o[n2o][1] * inv0);
        *(float2*)(r1p + n2o * 8) =
            make_float2(o[n2o][2] * inv1, o[n2o][3] * inv1);
    }
}

extern "C" void kernel_launch(void* const* d_in, const int* in_sizes, int n_in,
                              void* d_out, int out_size)
{
    const float* q = (const float*)d_in[0];
    const float* k = (const float*)d_in[1];
    const float* v = (const float*)d_in[2];
    float* out = (float*)d_out;

    cvt_kv<<<2048, 256>>>(k, v);

    cudaFuncSetAttribute(attn_hmma12,
                         cudaFuncAttributeMaxDynamicSharedMemorySize, SMEM_BYTES);
    dim3 grid(64, 8, 2);   // qb, kv, batch
    attn_hmma12<<<grid, 256, SMEM_BYTES>>>(q, out);
}

// round 16
// speedup vs baseline: 1.3236x; 1.3236x over previous
#include <cuda_runtime.h>
#include <cuda_fp16.h>
#include <cstdint>

#define SS   2048
#define DQ   4096
#define DKV  1024
#define SCL  (0.08838834764831845f * 1.4426950408889634f)

// smem: 3 K/V stages, 32KB each (K@+0, V@+16K). Q staged over stages 0-1.
#define SMEM_BYTES 98304

// fp16 K/V scratch: 4096 tokens x 1024 dims x 2B = 8MB each
__device__ uint4 g_kh[524288];
__device__ uint4 g_vh[524288];

__device__ __forceinline__ uint32_t smem_u32(const void* p) {
    uint32_t a;
    asm("{ .reg .u64 t; cvta.to.shared.u64 t, %1; cvt.u32.u64 %0, t; }" : "=r"(a) : "l"(p));
    return a;
}
__device__ __forceinline__ float fast_ex2(float x) {
    float y; asm("ex2.approx.ftz.f32 %0, %1;" : "=f"(y) : "f"(x)); return y;
}
__device__ __forceinline__ void ldsm_x4(uint32_t* r, uint32_t addr) {
    asm volatile("ldmatrix.sync.aligned.m8n8.x4.shared.b16 {%0,%1,%2,%3}, [%4];"
        : "=r"(r[0]), "=r"(r[1]), "=r"(r[2]), "=r"(r[3]) : "r"(addr));
}
__device__ __forceinline__ void ldsm_x4_t(uint32_t* r, uint32_t addr) {
    asm volatile("ldmatrix.sync.aligned.m8n8.x4.trans.shared.b16 {%0,%1,%2,%3}, [%4];"
        : "=r"(r[0]), "=r"(r[1]), "=r"(r[2]), "=r"(r[3]) : "r"(addr));
}
__device__ __forceinline__ void mma16816(float* d, const uint32_t* a, const uint32_t* b) {
    asm volatile("mma.sync.aligned.m16n8k16.row.col.f32.f16.f16.f32 "
        "{%0,%1,%2,%3},{%4,%5,%6,%7},{%8,%9},{%0,%1,%2,%3};"
        : "+f"(d[0]), "+f"(d[1]), "+f"(d[2]), "+f"(d[3])
        : "r"(a[0]), "r"(a[1]), "r"(a[2]), "r"(a[3]), "r"(b[0]), "r"(b[1]));
}
__device__ __forceinline__ uint32_t packh2(float a, float b) {
    __half2 h = __floats2half2_rn(a, b);
    return *(uint32_t*)&h;
}
__device__ __forceinline__ void cp16(uint32_t dst, const void* src) {
    asm volatile("cp.async.cg.shared.global [%0], [%1], 16;" :: "r"(dst), "l"(src));
}

// ---- K/V fp32 -> fp16 convert (one pass, 8 elems/thread/tensor) ----
__global__ void __launch_bounds__(256)
cvt_kv(const float* __restrict__ k, const float* __restrict__ v)
{
    size_t i = (size_t)blockIdx.x * 256 + threadIdx.x;   // 0..524287
    const float4* ks = (const float4*)k + 2 * i;
    float4 a = ks[0], c = ks[1];
    g_kh[i] = make_uint4(packh2(a.x, a.y), packh2(a.z, a.w),
                         packh2(c.x, c.y), packh2(c.z, c.w));
    const float4* vs = (const float4*)v + 2 * i;
    a = vs[0]; c = vs[1];
    g_vh[i] = make_uint4(packh2(a.x, a.y), packh2(a.z, a.w),
                         packh2(c.x, c.y), packh2(c.z, c.w));
}

// CTA: 4 heads x 32 tokens = 128 q-rows, 256 threads (8 warps), BN=64 keys/tile.
// Warp w: rows w*16..w*16+15 (head = w>>1, tokens q0 + (w&1)*16 ..).
// Each warp: S = Q(16xK) @ K^T(64 keys), exp in regs, O += P(reg) @ V (full hd).
// No P shared-memory roundtrip: QK C-fragments ARE the PV A-fragments.
// Diagonal tile: unrolled loops with warp-uniform guards (constant indices ->
// no register-array demotion), skipping fully-masked key chunks.
__global__ void __launch_bounds__(256, 1)
attn_hmma13(const float* __restrict__ q, float* __restrict__ out)
{
    extern __shared__ char sm[];
    const uint32_t sb = smem_u32(sm);

    const int tid  = threadIdx.x;
    const int warp = tid >> 5, lane = tid & 31;
    const int qb = 63 - (int)blockIdx.x;      // longest CTAs first
    const int kv = blockIdx.y, b = blockIdx.z;
    const int q0 = qb * 32;
    const int hbase = kv * 4;
    const int ntiles = (qb >> 1) + 1;
    const int m  = lane >> 3;

    // ---- stage Q fp16 (pre-scaled) into stage-0/1 region, 256B rows, swizzled ----
    #pragma unroll
    for (int it = 0; it < 8; ++it) {
        int id  = tid + 256 * it;
        int row = id >> 4, c16 = id & 15;
        int token = q0 + (row & 31);
        int head  = hbase + (row >> 5);
        const float4* gp = (const float4*)(q + (size_t)(b * SS + token) * DQ
                                             + head * 128 + c16 * 8);
        float4 f0 = gp[0], f1 = gp[1];
        uint32_t h0 = packh2(f0.x * SCL, f0.y * SCL);
        uint32_t h1 = packh2(f0.z * SCL, f0.w * SCL);
        uint32_t h2 = packh2(f1.x * SCL, f1.y * SCL);
        uint32_t h3 = packh2(f1.z * SCL, f1.w * SCL);
        uint32_t addr = sb + row * 256 + ((c16 ^ (row & 7)) << 4);
        asm volatile("st.shared.v4.b32 [%0],{%1,%2,%3,%4};"
            :: "r"(addr), "r"(h0), "r"(h1), "r"(h2), "r"(h3));
    }
    __syncthreads();

    // ---- persistent Q fragments, M=16: qf[kstep][4] (32 regs) ----
    uint32_t qf[8][4];
    {
        int row = warp * 16 + (lane & 7) + ((lane >> 3) & 1) * 8;
        #pragma unroll
        for (int ks = 0; ks < 8; ++ks) {
            int chunk = ks * 2 + (lane >> 4);
            ldsm_x4(qf[ks], sb + row * 256 + ((chunk ^ (row & 7)) << 4));
        }
    }
    __syncthreads();   // Q region free for cp.async stages

    // ---- cp.async one K/V tile into stage jt%3 (fp16 source, no regs held) ----
    auto issue = [&](int jt) {
        size_t base = ((size_t)(b * SS + jt * 64) * DKV + kv * 128) * 2;
        const char* gk = (const char*)g_kh + base;
        const char* gv = (const char*)g_vh + base;
        uint32_t st = sb + 32768u * (uint32_t)(jt % 3);
        #pragma unroll
        for (int i = 0; i < 4; ++i) {
            int idx = tid + 256 * i;
            int row = idx >> 4, c16 = idx & 15;
            uint32_t d = st + row * 256 + ((c16 ^ (row & 7)) << 4);
            size_t so = (size_t)row * (DKV * 2) + c16 * 16;
            cp16(d,         gk + so);
            cp16(d + 16384, gv + so);
        }
        asm volatile("cp.async.commit_group;" ::: "memory");
    };

    issue(0);
    if (1 < ntiles) issue(1);

    float o[16][4];                           // 64 regs
    #pragma unroll
    for (int i = 0; i < 16; ++i)
        #pragma unroll
        for (int j = 0; j < 4; ++j) o[i][j] = 0.0f;
    float lsum0 = 0.0f, lsum1 = 0.0f;

    const int tok0 = q0 + (warp & 1) * 16 + (lane >> 2);
    const int kgmax = q0 + (warp & 1) * 16 + 15;   // warp's max valid key

    for (int jt = 0; jt < ntiles; ++jt) {
        if (jt + 1 < ntiles) asm volatile("cp.async.wait_group 1;" ::: "memory");
        else                 asm volatile("cp.async.wait_group 0;" ::: "memory");
        __syncthreads();     // stage jt%3 visible CTA-wide (only barrier per tile)

        const uint32_t sK = sb + 32768u * (uint32_t)(jt % 3);
        const uint32_t sV = sK + 16384;

        float s[8][4];
        #pragma unroll
        for (int n2 = 0; n2 < 8; ++n2)
            #pragma unroll
            for (int j = 0; j < 4; ++j) s[n2][j] = 0.0f;

        uint32_t pa[4][4];

        if (jt + 1 < ntiles) {
            // ---- interior tile: branch-free (all keys valid for all rows) ----
            #pragma unroll
            for (int ks2 = 0; ks2 < 4; ++ks2) {
                #pragma unroll
                for (int n2 = 0; n2 < 8; ++n2) {
                    uint32_t kb[4];
                    int kr = n2 * 8 + (lane & 7);
                    int chunk = ks2 * 4 + m;
                    ldsm_x4(kb, sK + kr * 256 + ((chunk ^ (kr & 7)) << 4));
                    mma16816(s[n2], qf[2*ks2],   kb);
                    mma16816(s[n2], qf[2*ks2+1], kb + 2);
                }
            }
            #pragma unroll
            for (int n2 = 0; n2 < 8; ++n2) {
                float e0 = fast_ex2(s[n2][0]);
                float e1 = fast_ex2(s[n2][1]);
                float e2 = fast_ex2(s[n2][2]);
                float e3 = fast_ex2(s[n2][3]);
                lsum0 += e0 + e1;
                lsum1 += e2 + e3;
                pa[n2 >> 1][(n2 & 1) * 2]     = packh2(e0, e1);
                pa[n2 >> 1][(n2 & 1) * 2 + 1] = packh2(e2, e3);
            }

            if (jt + 2 < ntiles) issue(jt + 2);

            #pragma unroll
            for (int ks2 = 0; ks2 < 4; ++ks2) {
                int Vrow = ks2 * 16 + (m & 1) * 8 + (lane & 7);
                #pragma unroll
                for (int n2o = 0; n2o < 16; n2o += 2) {
                    uint32_t vb[4];
                    int chunk = n2o + (m >> 1);
                    ldsm_x4_t(vb, sV + Vrow * 256 + ((chunk ^ (Vrow & 7)) << 4));
                    mma16816(o[n2o],     pa[ks2], vb);
                    mma16816(o[n2o + 1], pa[ks2], vb + 2);
                }
            }
        } else {
            // ---- diagonal tile: unrolled + warp-uniform guards, const indices ----
            const int n2lim  = ((kgmax - jt * 64) >> 3) + 1;   // 2/4 (even qb), 6/8 (odd)
            const int ks2lim = ((kgmax - jt * 64) >> 4) + 1;   // 1/2 or 3/4

            #pragma unroll
            for (int ks2 = 0; ks2 < 4; ++ks2) {
                #pragma unroll
                for (int n2 = 0; n2 < 8; ++n2) {
                    if (n2 < n2lim) {
                        uint32_t kb[4];
                        int kr = n2 * 8 + (lane & 7);
                        int chunk = ks2 * 4 + m;
                        ldsm_x4(kb, sK + kr * 256 + ((chunk ^ (kr & 7)) << 4));
                        mma16816(s[n2], qf[2*ks2],   kb);
                        mma16816(s[n2], qf[2*ks2+1], kb + 2);
                    }
                }
            }
            // full masked softmax: skipped groups (s=0) are masked to exact 0
            #pragma unroll
            for (int n2 = 0; n2 < 8; ++n2) {
                int kg = jt * 64 + n2 * 8 + (lane & 3) * 2;
                float e0 = (kg     <= tok0)     ? fast_ex2(s[n2][0]) : 0.0f;
                float e1 = (kg + 1 <= tok0)     ? fast_ex2(s[n2][1]) : 0.0f;
                float e2 = (kg     <= tok0 + 8) ? fast_ex2(s[n2][2]) : 0.0f;
                float e3 = (kg + 1 <= tok0 + 8) ? fast_ex2(s[n2][3]) : 0.0f;
                lsum0 += e0 + e1;
                lsum1 += e2 + e3;
                pa[n2 >> 1][(n2 & 1) * 2]     = packh2(e0, e1);
                pa[n2 >> 1][(n2 & 1) * 2 + 1] = packh2(e2, e3);
            }

            // PV: only key-chunks containing any valid key (pa beyond is all-zero)
            #pragma unroll
            for (int ks2 = 0; ks2 < 4; ++ks2) {
                if (ks2 < ks2lim) {
                    int Vrow = ks2 * 16 + (m & 1) * 8 + (lane & 7);
                    #pragma unroll
                    for (int n2o = 0; n2o < 16; n2o += 2) {
                        uint32_t vb[4];
                        int chunk = n2o + (m >> 1);
                        ldsm_x4_t(vb, sV + Vrow * 256 + ((chunk ^ (Vrow & 7)) << 4));
                        mma16816(o[n2o],     pa[ks2], vb);
                        mma16816(o[n2o + 1], pa[ks2], vb + 2);
                    }
                }
            }
        }
    }

    // ---- epilogue: reduce l over the 4 lanes sharing a row, normalize, store ----
    lsum0 += __shfl_xor_sync(0xffffffffu, lsum0, 1);
    lsum0 += __shfl_xor_sync(0xffffffffu, lsum0, 2);
    lsum1 += __shfl_xor_sync(0xffffffffu, lsum1, 1);
    lsum1 += __shfl_xor_sync(0xffffffffu, lsum1, 2);
    float inv0 = 1.0f / lsum0, inv1 = 1.0f / lsum1;

    const int head = hbase + (warp >> 1);
    float* r0p = out + (size_t)(b * SS + tok0) * DQ + head * 128 + (lane & 3) * 2;
    float* r1p = r0p + (size_t)8 * DQ;
    #pragma unroll
    for (int n2o = 0; n2o < 16; ++n2o) {
        *(float2*)(r0p + n2o * 8) =
            make_float2(o[n2o][0] * inv0, o[n2o][1] * inv0);
        *(float2*)(r1p + n2o * 8) =
            make_float2(o[n2o][2] * inv1, o[n2o][3] * inv1);
    }
}

extern "C" void kernel_launch(void* const* d_in, const int* in_sizes, int n_in,
                              void* d_out, int out_size)
{
    const float* q = (const float*)d_in[0];
    const float* k = (const float*)d_in[1];
    const float* v = (const float*)d_in[2];
    float* out = (float*)d_out;

    cvt_kv<<<2048, 256>>>(k, v);

    cudaFuncSetAttribute(attn_hmma13,
                         cudaFuncAttributeMaxDynamicSharedMemorySize, SMEM_BYTES);
    dim3 grid(64, 8, 2);   // qb, kv, batch
    attn_hmma13<<<grid, 256, SMEM_BYTES>>>(q, out);
}